// round 10
// baseline (speedup 1.0000x reference)
#include <cuda_runtime.h>
#include <cuda_bf16.h>
#include <cstdint>

#define EDGES 300000
#define HDIM 128
#define L1_ROWS 1528000   // sum of n_dst over the 22 layer-1 relations

#if defined(__CUDA_ARCH_FEAT_SM103_ALL) || defined(__CUDA_ARCH_FEAT_SM101_ALL) || defined(__CUDA_ARCH_FEAT_SM100_ALL)
#define USE_TC 1
#else
#define USE_TC 0
#endif

// ---------------- static graph metadata -------------------------------------
static const int NODE_N[10] = {50000,2000,80000,10000,2000,150000,120000,100000,60000,40000};
struct RelDef { int s, d, ei, flip; };
static const RelDef REL[26] = {
  {0,1,0,0},{1,0,0,1},{0,2,1,0},{2,0,1,1},{0,3,2,0},{3,0,2,1},
  {0,4,3,0},{4,0,3,1},{0,5,4,0},{5,0,4,1},{0,6,5,0},{6,0,5,1},
  {6,7,6,0},{7,6,6,1},{5,6,7,0},{6,5,7,1},{5,7,8,0},{7,5,8,1},
  {4,5,9,0},{5,4,9,1},{4,3,10,0},{3,4,10,1},{2,8,11,0},{8,2,11,1},
  {2,9,12,0},{9,2,12,1}};
static const int L1_RELS[22] = {0,1,2,3,4,5,6,7,8,9,10,11,13,14,15,17,18,19,20,21,23,25};
static const int L2_RELS[6] = {1,3,5,7,9,11};

// ---------------- device scratch ---------------------------------------------
__device__ __align__(256) float g_ZBUF[(size_t)L1_ROWS * HDIM + L1_ROWS];
#define AGG_PTR   (g_ZBUF)
#define DEG_PTR   (g_ZBUF + (size_t)L1_ROWS * HDIM)
__device__ __align__(256) float g_XBUF[(size_t)414000 * HDIM];
__device__ __align__(256) float g_CRS[(size_t)50000 * HDIM];
__device__ float g_BSUM[8 * 128];
__device__ __align__(256) __nv_bfloat16 g_Bimg[36 * 32768];

// ---------------- param structs ------------------------------------------------
struct ScatParams {
  const int*   ei[22];
  const float* xsrc[22];
  long long    aggOff[22];
  int          flip[22];
};
struct GemmParams {
  int nJobs, relu;
  int rowBlkStart[8];
  int nRows[7];
  const float* xCur[7];
  float*       outPtr[7];
  int          bsumIdx[7];
  int          nRel[7];
  int          bimg[7][7];
  const float* wlRaw[7][6];
  long long    aggOff[7][6];
  long long    degOff[7][6];
};
struct BPrepParams {
  const float* src[36][6];
  int nSrc[36];
  const float* bsrc[8][6];
  int bN[8];
};

// ---------------- PTX helpers (arch-guarded) -----------------------------------
#if USE_TC
__device__ __forceinline__ uint32_t smem_u32(const void* p) {
  uint32_t a;
  asm("{ .reg .u64 t; cvta.to.shared.u64 t, %1; cvt.u32.u64 %0, t; }" : "=r"(a) : "l"(p));
  return a;
}
__device__ __forceinline__ int elect_one() {
  uint32_t p;
  asm volatile("{ .reg .pred P; elect.sync _|P, 0xFFFFFFFF; selp.b32 %0, 1, 0, P; }" : "=r"(p));
  return (int)p;
}
__device__ __forceinline__ uint64_t make_desc(uint32_t addr) {
  return 0x4000404000010000ULL | (uint64_t)((addr >> 4) & 0x3FFF);
}
__device__ __forceinline__ void mma_f16_ts(uint32_t d, uint32_t a_tmem, uint64_t b,
                                           uint32_t idesc, uint32_t en) {
  asm volatile(
    "{\n\t.reg .pred p;\n\t"
    "setp.ne.u32 p, %4, 0;\n\t"
    "tcgen05.mma.cta_group::1.kind::f16 [%0], [%1], %2, %3, {%5, %5, %5, %5}, p;\n\t}"
    :: "r"(d), "r"(a_tmem), "l"(b), "r"(idesc), "r"(en), "r"(0u) : "memory");
}
__device__ __forceinline__ void mbar_init(uint32_t mbar, uint32_t cnt) {
  asm volatile("mbarrier.init.shared.b64 [%0], %1;" :: "r"(mbar), "r"(cnt) : "memory");
}
__device__ __forceinline__ void mbar_inval(uint32_t mbar) {
  asm volatile("mbarrier.inval.shared.b64 [%0];" :: "r"(mbar) : "memory");
}
__device__ __forceinline__ void mbar_wait(uint32_t mbar, uint32_t parity) {
  asm volatile(
    "{\n\t.reg .pred P;\n\t"
    "WL_%=:\n\t"
    "mbarrier.try_wait.parity.acquire.cta.shared::cta.b64 P, [%0], %1, 0x989680;\n\t"
    "@P bra WD_%=;\n\t"
    "bra WL_%=;\n\t"
    "WD_%=:\n\t}\n"
    :: "r"(mbar), "r"(parity) : "memory");
}
__device__ __forceinline__ void tc_commit(uint32_t mbar) {
  asm volatile(
    "tcgen05.commit.cta_group::1.mbarrier::arrive::one.shared::cluster.b64 [%0];"
    :: "r"(mbar) : "memory");
}
// 64KB bulk copy global->smem, completion on mbar (expect_tx + UBLKCP)
__device__ __forceinline__ void bulkB(uint32_t dst, const void* src, uint32_t mbar) {
  asm volatile("mbarrier.arrive.expect_tx.shared.b64 _, [%0], %1;"
               :: "r"(mbar), "r"(65536u) : "memory");
  asm volatile(
    "{\n\t.reg .u64 gs;\n\t"
    "cvta.to.global.u64 gs, %1;\n\t"
    "cp.async.bulk.shared::cta.global.mbarrier::complete_tx::bytes [%0], [gs], %2, [%3];\n\t}"
    :: "r"(dst), "l"(src), "r"(65536u), "r"(mbar) : "memory");
}
#define TC_ALLOC(sm, n)   asm volatile("tcgen05.alloc.cta_group::1.sync.aligned.shared::cta.b32 [%0], %1;" :: "r"(sm), "r"(n) : "memory")
#define TC_DEALLOC(t, n)  asm volatile("tcgen05.dealloc.cta_group::1.sync.aligned.b32 %0, %1;" :: "r"(t), "r"(n))
#define TC_RELINQ()       asm volatile("tcgen05.relinquish_alloc_permit.cta_group::1.sync.aligned;")
#define TC_FENCE_AFTER()  asm volatile("tcgen05.fence::after_thread_sync;" ::: "memory")
#define TC_FENCE_BEFORE() asm volatile("tcgen05.fence::before_thread_sync;" ::: "memory")
#define TC_WAIT_LD()      asm volatile("tcgen05.wait::ld.sync.aligned;" ::: "memory")
#define TC_WAIT_ST()      asm volatile("tcgen05.wait::st.sync.aligned;" ::: "memory")

#define TCGEN05_ST_32X32B_X16(tmem_addr, r) \
  asm volatile( \
    "tcgen05.st.sync.aligned.32x32b.x16.b32 [%0], " \
    "{%1, %2, %3, %4, %5, %6, %7, %8, " \
    " %9, %10, %11, %12, %13, %14, %15, %16};" \
    :: "r"(tmem_addr), \
       "r"((r)[0]),  "r"((r)[1]),  "r"((r)[2]),  "r"((r)[3]), \
       "r"((r)[4]),  "r"((r)[5]),  "r"((r)[6]),  "r"((r)[7]), \
       "r"((r)[8]),  "r"((r)[9]),  "r"((r)[10]), "r"((r)[11]), \
       "r"((r)[12]), "r"((r)[13]), "r"((r)[14]), "r"((r)[15]) \
    : "memory")

#define LDTM_X32(r, addr) \
  asm volatile( \
    "tcgen05.ld.sync.aligned.32x32b.x32.b32 " \
    "{%0, %1, %2, %3, %4, %5, %6, %7, " \
    " %8, %9, %10, %11, %12, %13, %14, %15, " \
    " %16, %17, %18, %19, %20, %21, %22, %23, " \
    " %24, %25, %26, %27, %28, %29, %30, %31}, [%32];" \
    : "=r"((r)[0]),  "=r"((r)[1]),  "=r"((r)[2]),  "=r"((r)[3]), \
      "=r"((r)[4]),  "=r"((r)[5]),  "=r"((r)[6]),  "=r"((r)[7]), \
      "=r"((r)[8]),  "=r"((r)[9]),  "=r"((r)[10]), "=r"((r)[11]), \
      "=r"((r)[12]), "=r"((r)[13]), "=r"((r)[14]), "=r"((r)[15]), \
      "=r"((r)[16]), "=r"((r)[17]), "=r"((r)[18]), "=r"((r)[19]), \
      "=r"((r)[20]), "=r"((r)[21]), "=r"((r)[22]), "=r"((r)[23]), \
      "=r"((r)[24]), "=r"((r)[25]), "=r"((r)[26]), "=r"((r)[27]), \
      "=r"((r)[28]), "=r"((r)[29]), "=r"((r)[30]), "=r"((r)[31]) \
    : "r"(addr))

#define MMA_IDESC 0x8200490u

// TMEM columns (256 per CTA): D @0..127, Ahi @128..191, Alo @192..255
#define TM_D    0u
#define TM_AHI  128u
#define TM_ALO  192u

__device__ __forceinline__ uint32_t pack_hi(float a, float b, float& ra, float& rb) {
  __nv_bfloat16 ha = __float2bfloat16(a), hb = __float2bfloat16(b);
  ra = a - __bfloat162float(ha); rb = b - __bfloat162float(hb);
  return (uint32_t)__bfloat16_as_ushort(ha) | ((uint32_t)__bfloat16_as_ushort(hb) << 16);
}
__device__ __forceinline__ uint32_t pack_bf(float a, float b) {
  __nv_bfloat16 ha = __float2bfloat16(a), hb = __float2bfloat16(b);
  return (uint32_t)__bfloat16_as_ushort(ha) | ((uint32_t)__bfloat16_as_ushort(hb) << 16);
}
#endif  // USE_TC

// smem layout; padded so exactly 2 CTAs/SM co-reside (TMEM = 2 x 256 cols)
#define SM_TMEM   0
#define SM_CBAR   8
#define SM_BBAR   16
#define SM_B0     1024
#define SM_BYTES  100352   // 98KB -> floor(227KB / 98KB) = 2 CTAs/SM

// ---------------- simple kernels ------------------------------------------------
__global__ void deg_kernel(ScatParams S) {
  int rel = blockIdx.y;
  int e = blockIdx.x * blockDim.x + threadIdx.x;
  if (e >= EDGES) return;
  const int* ei = S.ei[rel];
  int dstRow = S.flip[rel] ? 0 : EDGES;
  int dst = __ldg(ei + dstRow + e);
  atomicAdd(DEG_PTR + S.aggOff[rel] + dst, 1.0f);
}

__global__ void scatter_kernel(ScatParams S) {
  int rel  = blockIdx.y;
  int lane = threadIdx.x & 31;
  int warp = threadIdx.x >> 5;
  const int* ei   = S.ei[rel];
  const float* xs = S.xsrc[rel];
  float* aggBase  = AGG_PTR + (size_t)S.aggOff[rel] * HDIM;
  int srcRow = S.flip[rel] ? EDGES : 0;
  int dstRow = EDGES - srcRow;
  int e0 = blockIdx.x * 8 + warp;
#pragma unroll
  for (int i = 0; i < 4; ++i) {
    int e   = e0 + i * 75000;
    int src = __ldg(ei + srcRow + e);
    int dst = __ldg(ei + dstRow + e);
    float4 v = __ldg(reinterpret_cast<const float4*>(xs + (size_t)src * HDIM) + lane);
    float* p = aggBase + (size_t)dst * HDIM + lane * 4;
    asm volatile("red.global.add.v4.f32 [%0], {%1,%2,%3,%4};"
                 :: "l"(p), "f"(v.x), "f"(v.y), "f"(v.z), "f"(v.w) : "memory");
  }
}

// ---------------- weight image prep (sum + f32 -> swizzled bf16 hi/lo) --------
__global__ void bprep_kernel(BPrepParams P) {
  if (blockIdx.x == 36) {
    if (blockIdx.y == 0 && threadIdx.x < 128) {
      for (int j = 0; j < 8; ++j) {
        float s = 0.f;
        for (int q = 0; q < P.bN[j]; ++q) s += __ldg(P.bsrc[j][q] + threadIdx.x);
        g_BSUM[j * 128 + threadIdx.x] = s;
      }
    }
    return;
  }
  int img = blockIdx.x;
  int n = P.nSrc[img];
  char* dst = (char*)g_Bimg + (size_t)img * 65536;
  int lo = blockIdx.y * 4096;
  int hi = lo + 4096;
  for (int idx = lo + threadIdx.x; idx < hi; idx += blockDim.x) {
    int k = idx >> 7, nn = idx & 127;
    float v = 0.f;
    for (int q = 0; q < n; ++q) v += __ldg(P.src[img][q] + idx);
    __nv_bfloat16 h = __float2bfloat16(v);
    __nv_bfloat16 l = __float2bfloat16(v - __bfloat162float(h));
    uint32_t atom = (uint32_t)(nn >> 3) + (uint32_t)(k >> 6) * 16u;
    uint32_t off  = atom * 1024u + (uint32_t)(nn & 7) * 128u + (uint32_t)(k & 63) * 2u;
    uint32_t sw   = off ^ ((off >> 3) & 0x70);
    *(unsigned short*)(dst + sw)         = __bfloat16_as_ushort(h);
    *(unsigned short*)(dst + 32768 + sw) = __bfloat16_as_ushort(l);
  }
}

// ---------------- persistent fused GEMM: 2 CTAs/SM x 128 threads ----------------
// Each CTA: TMEM 256 (D + single A hi/lo), one 64KB B smem buffer (cp.async.bulk),
// serial chunk loop. The two co-resident CTAs dovetail: one CTA's MMA phase hides
// the other's A-prep latency. Reg budget 256/thread guarantees co-residency.
__global__ __launch_bounds__(128, 2) void gemm_kernel(GemmParams P) {
  extern __shared__ char smem[];
  int tid = threadIdx.x;
  int nTiles = P.rowBlkStart[P.nJobs];

#if USE_TC
  uint32_t sbase = smem_u32(smem);
  int wid = tid >> 5;

  if (wid == 0) { TC_ALLOC(sbase + SM_TMEM, 256); TC_RELINQ(); }
  if (tid == 0) { mbar_init(sbase + SM_CBAR, 1); mbar_init(sbase + SM_BBAR, 1); }
  __syncthreads();
  uint32_t tmem;
  asm volatile("ld.shared.b32 %0, [%1];" : "=r"(tmem) : "r"(sbase + SM_TMEM));

  uint32_t woff = ((uint32_t)wid & 3u) << 21;
  uint64_t db_hi = make_desc(sbase + SM_B0);
  uint64_t db_lo = make_desc(sbase + SM_B0 + 32768);

  auto jobOf = [&](int t) {
    int jj = 0;
#pragma unroll
    for (int q = 1; q < 7; ++q)
      if (q < P.nJobs && t >= P.rowBlkStart[q]) jj = q;
    return jj;
  };

  // prepA: one full 128-float row per thread; all 32 LDG.128 issued up-front
  // (MLP=32), then convert hi/lo + 8x STTM.x16 into the single A TMEM buffer.
  auto prepA = [&](int c, int j, int row0, int nrows) {
    int gr = row0 + tid;
    bool av = gr < nrows;
    const float* Ab;
    const float* deg = nullptr;
    if (c == 0) Ab = P.xCur[j];
    else { Ab = AGG_PTR + (size_t)P.aggOff[j][c - 1] * HDIM; deg = DEG_PTR + P.degOff[j][c - 1]; }
    float sc = 1.0f;
    if (deg && av) sc = 1.0f / fmaxf(__ldg(deg + gr), 1.0f);
    const float4* asrc = reinterpret_cast<const float4*>(Ab + (size_t)gr * HDIM);
    float4 v[32];
#pragma unroll
    for (int i = 0; i < 32; ++i) {
      v[i] = make_float4(0.f, 0.f, 0.f, 0.f);
      if (av) v[i] = __ldg(asrc + i);
    }
#pragma unroll
    for (int g = 0; g < 4; ++g) {
      uint32_t hv[16], lv[16];
#pragma unroll
      for (int i = 0; i < 8; ++i) {
        float4 t = v[g * 8 + i];
        float ax = t.x * sc, ay = t.y * sc, az = t.z * sc, aw = t.w * sc;
        float rx, ry, rz, rw;
        hv[2 * i]     = pack_hi(ax, ay, rx, ry);
        hv[2 * i + 1] = pack_hi(az, aw, rz, rw);
        lv[2 * i]     = pack_bf(rx, ry);
        lv[2 * i + 1] = pack_bf(rz, rw);
      }
      uint32_t coff = (uint32_t)(g * 16);
      TCGEN05_ST_32X32B_X16(tmem + TM_AHI + coff + woff, hv);
      TCGEN05_ST_32X32B_X16(tmem + TM_ALO + coff + woff, lv);
    }
    TC_WAIT_ST();
    TC_FENCE_BEFORE();
  };

  auto dispatch = [&](int c) {    // warp 0 elected thread
    TC_FENCE_AFTER();
    uint32_t en = (c > 0) ? 1u : 0u;
#pragma unroll
    for (int ks = 0; ks < 8; ++ks) {
      uint64_t boff = (ks < 4) ? (uint64_t)(ks * 2) : (uint64_t)(1024 + (ks - 4) * 2);
      uint32_t ahi = tmem + TM_AHI + (uint32_t)ks * 8u;
      uint32_t alo = tmem + TM_ALO + (uint32_t)ks * 8u;
      mma_f16_ts(tmem + TM_D, ahi, db_hi + boff, MMA_IDESC, en); en = 1u;
      mma_f16_ts(tmem + TM_D, ahi, db_lo + boff, MMA_IDESC, 1u);
      mma_f16_ts(tmem + TM_D, alo, db_hi + boff, MMA_IDESC, 1u);
    }
    tc_commit(sbase + SM_CBAR);
  };

  // epilogue: warp w = subpartition w, 4 col-blocks each
  auto epilogue = [&](int j, int row0, int nrows) {
    TC_FENCE_AFTER();
    int lid = tid & 31;
    int gr = row0 + wid * 32 + lid;
    const float* bs = g_BSUM + P.bsumIdx[j] * 128;
    float* op = P.outPtr[j] + (size_t)gr * HDIM;
#pragma unroll
    for (int nb = 0; nb < 4; ++nb) {
      uint32_t dr[32];
      LDTM_X32(dr, tmem + TM_D + nb * 32);
      TC_WAIT_LD();
      if (gr < nrows) {
#pragma unroll
        for (int q = 0; q < 32; q += 4) {
          float4 o;
          o.x = __uint_as_float(dr[q + 0]) + __ldg(bs + nb * 32 + q + 0);
          o.y = __uint_as_float(dr[q + 1]) + __ldg(bs + nb * 32 + q + 1);
          o.z = __uint_as_float(dr[q + 2]) + __ldg(bs + nb * 32 + q + 2);
          o.w = __uint_as_float(dr[q + 3]) + __ldg(bs + nb * 32 + q + 3);
          if (P.relu) {
            o.x = fmaxf(o.x, 0.f); o.y = fmaxf(o.y, 0.f);
            o.z = fmaxf(o.z, 0.f); o.w = fmaxf(o.w, 0.f);
          }
          *reinterpret_cast<float4*>(op + nb * 32 + q) = o;
        }
      }
    }
    TC_FENCE_BEFORE();
  };

  uint32_t pc = 0, pb = 0;
  int tile = blockIdx.x;

  // prologue: issue B for the first chunk
  if (tile < nTiles && tid == 0) {
    int j0 = jobOf(tile);
    bulkB(sbase + SM_B0, (const char*)g_Bimg + (size_t)P.bimg[j0][0] * 65536,
          sbase + SM_BBAR);
  }

  for (; tile < nTiles; tile += gridDim.x) {
    int j = jobOf(tile);
    int row0  = (tile - P.rowBlkStart[j]) * 128;
    int nrows = P.nRows[j];
    int nCh = P.nRel[j] + 1;

    for (int c = 0; c < nCh; ++c) {
      prepA(c, j, row0, nrows);          // all 128 threads
      __syncthreads();
      if (wid == 0 && elect_one()) {
        mbar_wait(sbase + SM_BBAR, pb);  // B(c) bulk landed
        dispatch(c);
      }
      pb ^= 1;
      mbar_wait(sbase + SM_CBAR, pc); pc ^= 1;   // MMAs(c) done: A TMEM + B smem free
      if (tid == 0) {                    // issue next chunk's B
        int nc = c + 1, nt = tile;
        if (nc == nCh) { nc = 0; nt = tile + gridDim.x; }
        if (nt < nTiles) {
          int nj = (nc == 0) ? jobOf(nt) : j;
          bulkB(sbase + SM_B0, (const char*)g_Bimg + (size_t)P.bimg[nj][nc] * 65536,
                sbase + SM_BBAR);
        }
      }
    }
    epilogue(j, row0, nrows);
    __syncthreads();                     // D reads complete before next tile's MMA
  }

  __syncthreads();
  if (tid == 0) { mbar_inval(sbase + SM_CBAR); mbar_inval(sbase + SM_BBAR); }
  __syncthreads();
  if (wid == 0) TC_DEALLOC(tmem, 256);

#else  // ---------------- FFMA fallback (non-"a" pass; never executes) ----------
  // simple correct version: row per thread, 32-column passes
  for (int tile = blockIdx.x; tile < nTiles; tile += gridDim.x) {
    int j = 0;
#pragma unroll
    for (int q = 1; q < 7; ++q)
      if (q < P.nJobs && tile >= P.rowBlkStart[q]) j = q;
    int row0  = (tile - P.rowBlkStart[j]) * 128;
    int nrows = P.nRows[j];
    int gr = row0 + tid;
    if (gr >= nrows) continue;
    const float* bs = g_BSUM + P.bsumIdx[j] * 128;
    float* op = P.outPtr[j] + (size_t)gr * HDIM;
    int nChunks = P.nRel[j] + 1;
    for (int nb = 0; nb < 4; ++nb) {
      float acc[32];
#pragma unroll
      for (int q = 0; q < 32; ++q) acc[q] = bs[nb * 32 + q];
      for (int c = 0; c < nChunks; ++c) {
        const float* Ab;
        const float* Bb;
        const float* deg = nullptr;
        if (c == 0) { Ab = P.xCur[j]; Bb = nullptr; }
        else {
          Ab  = AGG_PTR + (size_t)P.aggOff[j][c - 1] * HDIM;
          Bb  = P.wlRaw[j][c - 1];
          deg = DEG_PTR + P.degOff[j][c - 1];
        }
        float s = deg ? (1.0f / fmaxf(__ldg(deg + gr), 1.0f)) : 1.0f;
        for (int k = 0; k < 128; ++k) {
          float a = __ldg(Ab + (size_t)gr * HDIM + k) * s;
          if (c == 0) {
            // Wr-sum chunk not materialized in fallback; approximate via wlRaw? skip
          } else {
            const float* br = Bb + (size_t)k * HDIM + nb * 32;
#pragma unroll
            for (int q = 0; q < 32; ++q) acc[q] += a * __ldg(br + q);
          }
        }
      }
      for (int q = 0; q < 32; ++q) {
        float o = acc[q];
        if (P.relu) o = fmaxf(o, 0.f);
        op[nb * 32 + q] = o;
      }
    }
  }
#endif
}

// final: out[50000,64] = CRS[50000,128] @ linW[128,64] + linb
__global__ void final_kernel(const float* __restrict__ W,
                             const float* __restrict__ b,
                             float* __restrict__ out) {
  __shared__ float sW[128 * 64];
  __shared__ float sx[4][128];
  int tid = threadIdx.x;
  for (int i = tid; i < 128 * 64; i += 256) sW[i] = W[i];
  int n = tid & 63, rl = tid >> 6;
  int row = blockIdx.x * 4 + rl;
  for (int k = n; k < 128; k += 64)
    sx[rl][k] = (row < 50000) ? g_CRS[(size_t)row * HDIM + k] : 0.f;
  __syncthreads();
  float acc = 0.f;
#pragma unroll 16
  for (int k = 0; k < 128; ++k) acc += sx[rl][k] * sW[k * 64 + n];
  if (row < 50000) out[(size_t)row * 64 + n] = acc + b[n];
}

// ---------------- launch --------------------------------------------------------
extern "C" void kernel_launch(void* const* d_in, const int* in_sizes, int n_in,
                              void* d_out, int out_size) {
  (void)in_sizes; (void)n_in; (void)out_size;
  const float* X[10];
  for (int t = 0; t < 10; ++t) X[t] = (const float*)d_in[t];
  const int* EI[13];
  for (int i = 0; i < 13; ++i) EI[i] = (const int*)d_in[10 + i];
  const float* Wl   = (const float*)d_in[23];
  const float* bl   = (const float*)d_in[24];
  const float* Wr   = (const float*)d_in[25];
  const float* linW = (const float*)d_in[26];
  const float* linb = (const float*)d_in[27];
  float* out = (float*)d_out;

  void *pZBUF = 0, *pXBUF = 0, *pCRS = 0;
  cudaGetSymbolAddress(&pZBUF, g_ZBUF);
  cudaGetSymbolAddress(&pXBUF, g_XBUF);
  cudaGetSymbolAddress(&pCRS, g_CRS);
  float* XBUF = (float*)pXBUF;
  float* CRS = (float*)pCRS;

  cudaFuncSetAttribute(gemm_kernel, cudaFuncAttributeMaxDynamicSharedMemorySize, SM_BYTES);

  static const int TYPE_OFF[7] = {0, 50000, 52000, 132000, 142000, 144000, 294000};

  long long degOff[26];
  {
    long long cum = 0;
    for (int k = 0; k < 22; ++k) { int r = L1_RELS[k]; degOff[r] = cum; cum += NODE_N[REL[r].d]; }
  }

  ScatParams s1 = {};
  for (int k = 0; k < 22; ++k) {
    int r = L1_RELS[k];
    s1.ei[k] = EI[REL[r].ei];
    s1.xsrc[k] = X[REL[r].s];
    s1.aggOff[k] = degOff[r];
    s1.flip[k] = REL[r].flip;
  }
  ScatParams s2 = {};
  for (int k = 0; k < 6; ++k) {
    int r = L2_RELS[k];
    s2.ei[k] = EI[REL[r].ei];
    s2.xsrc[k] = XBUF + (size_t)TYPE_OFF[REL[r].s] * HDIM;
    s2.aggOff[k] = (long long)k * 50000;
    s2.flip[k] = REL[r].flip;
  }

  BPrepParams bp = {};
  int img = 0;

  GemmParams g1 = {};
  g1.nJobs = 7; g1.relu = 1;
  int cumblk = 0;
  for (int t = 0; t < 7; ++t) {
    g1.rowBlkStart[t] = cumblk;
    cumblk += (NODE_N[t] + 127) / 128;
    g1.nRows[t] = NODE_N[t];
    g1.xCur[t] = X[t];
    g1.outPtr[t] = XBUF + (size_t)TYPE_OFF[t] * HDIM;
    g1.bsumIdx[t] = t;
    int n = 0;
    g1.bimg[t][0] = img;
    for (int k = 0; k < 22; ++k) {
      int r = L1_RELS[k];
      if (REL[r].d == t) { bp.src[img][n] = Wr + (size_t)r * 16384; ++n; }
    }
    bp.nSrc[img] = n; ++img;
    n = 0;
    for (int k = 0; k < 22; ++k) {
      int r = L1_RELS[k];
      if (REL[r].d == t) {
        g1.bimg[t][1 + n] = img;
        bp.src[img][0] = Wl + (size_t)r * 16384; bp.nSrc[img] = 1; ++img;
        g1.wlRaw[t][n] = Wl + (size_t)r * 16384;
        g1.aggOff[t][n] = degOff[r];
        g1.degOff[t][n] = degOff[r];
        ++n;
      }
    }
    g1.nRel[t] = n;
  }
  g1.rowBlkStart[7] = cumblk;

  GemmParams g2 = {};
  g2.nJobs = 1; g2.relu = 1;
  int g2blocks = (NODE_N[0] + 127) / 128;
  g2.rowBlkStart[0] = 0; g2.rowBlkStart[1] = g2blocks;
  g2.nRows[0] = NODE_N[0];
  g2.xCur[0] = XBUF;
  g2.outPtr[0] = CRS;
  g2.bsumIdx[0] = 7;
  g2.nRel[0] = 6;
  g2.bimg[0][0] = img;
  for (int k = 0; k < 6; ++k) bp.src[img][k] = Wr + ((size_t)26 + L2_RELS[k]) * 16384;
  bp.nSrc[img] = 6; ++img;
  for (int k = 0; k < 6; ++k) {
    int r = L2_RELS[k];
    g2.bimg[0][1 + k] = img;
    bp.src[img][0] = Wl + ((size_t)26 + r) * 16384; bp.nSrc[img] = 1; ++img;
    g2.wlRaw[0][k] = Wl + ((size_t)26 + r) * 16384;
    g2.aggOff[0][k] = (long long)k * 50000;
    g2.degOff[0][k] = degOff[r];
  }
  int nImgs = img;   // 36

  for (int t = 0; t < 7; ++t) {
    int n = 0;
    for (int k = 0; k < 22; ++k) {
      int r = L1_RELS[k];
      if (REL[r].d == t) bp.bsrc[t][n++] = bl + (size_t)r * 128;
    }
    bp.bN[t] = n;
  }
  for (int k = 0; k < 6; ++k) bp.bsrc[7][k] = bl + ((size_t)26 + L2_RELS[k]) * 128;
  bp.bN[7] = 6;

  // ---- execution ----
  cudaMemsetAsync(pZBUF, 0, ((size_t)L1_ROWS * HDIM + L1_ROWS) * sizeof(float), 0);
  deg_kernel<<<dim3((EDGES + 255) / 256, 22), 256>>>(s1);
  bprep_kernel<<<dim3(nImgs + 1, 4), 256>>>(bp);
  scatter_kernel<<<dim3(9375, 22), 256>>>(s1);
  gemm_kernel<<<296, 128, SM_BYTES>>>(g1);

  cudaMemsetAsync(pZBUF, 0, (size_t)300000 * HDIM * sizeof(float), 0);
  scatter_kernel<<<dim3(9375, 6), 256>>>(s2);
  gemm_kernel<<<296, 128, SM_BYTES>>>(g2);
  final_kernel<<<(50000 + 3) / 4, 256>>>(linW, linb, out);
}

// round 11
// speedup vs baseline: 1.0457x; 1.0457x over previous
#include <cuda_runtime.h>
#include <cuda_bf16.h>
#include <cuda_fp16.h>
#include <cstdint>

#define EDGES 300000
#define HDIM 128
#define L1_ROWS 1528000   // sum of n_dst over the 22 layer-1 relations

#if defined(__CUDA_ARCH_FEAT_SM103_ALL) || defined(__CUDA_ARCH_FEAT_SM101_ALL) || defined(__CUDA_ARCH_FEAT_SM100_ALL)
#define USE_TC 1
#else
#define USE_TC 0
#endif

// ---------------- static graph metadata -------------------------------------
static const int NODE_N[10] = {50000,2000,80000,10000,2000,150000,120000,100000,60000,40000};
struct RelDef { int s, d, ei, flip; };
static const RelDef REL[26] = {
  {0,1,0,0},{1,0,0,1},{0,2,1,0},{2,0,1,1},{0,3,2,0},{3,0,2,1},
  {0,4,3,0},{4,0,3,1},{0,5,4,0},{5,0,4,1},{0,6,5,0},{6,0,5,1},
  {6,7,6,0},{7,6,6,1},{5,6,7,0},{6,5,7,1},{5,7,8,0},{7,5,8,1},
  {4,5,9,0},{5,4,9,1},{4,3,10,0},{3,4,10,1},{2,8,11,0},{8,2,11,1},
  {2,9,12,0},{9,2,12,1}};
static const int L1_RELS[22] = {0,1,2,3,4,5,6,7,8,9,10,11,13,14,15,17,18,19,20,21,23,25};
static const int L2_RELS[6] = {1,3,5,7,9,11};

// ---------------- device scratch ---------------------------------------------
__device__ __align__(256) float g_ZBUF[(size_t)L1_ROWS * HDIM + L1_ROWS];
#define AGG_PTR   (g_ZBUF)
#define DEG_PTR   (g_ZBUF + (size_t)L1_ROWS * HDIM)
__device__ __align__(256) float g_XBUF[(size_t)414000 * HDIM];
__device__ __align__(256) float g_CRS[(size_t)50000 * HDIM];
__device__ float g_BSUM[8 * 128];
// 36 weight-chunk images, each 32KB fp16 (hi only), swizzled blocked-atom layout
__device__ __align__(256) __half g_Bimg[36 * 16384];

// ---------------- param structs ------------------------------------------------
struct ScatParams {
  const int*   ei[22];
  const float* xsrc[22];
  long long    aggOff[22];
  int          flip[22];
};
struct GemmParams {
  int nJobs, relu;
  int rowBlkStart[8];
  int nRows[7];
  const float* xCur[7];
  float*       outPtr[7];
  int          bsumIdx[7];
  int          nRel[7];
  int          bimg[7][7];
  long long    aggOff[7][6];
  long long    degOff[7][6];
};
struct BPrepParams {
  const float* src[36][6];
  int nSrc[36];
  const float* bsrc[8][6];
  int bN[8];
};

// ---------------- PTX helpers (arch-guarded) -----------------------------------
#if USE_TC
__device__ __forceinline__ uint32_t smem_u32(const void* p) {
  uint32_t a;
  asm("{ .reg .u64 t; cvta.to.shared.u64 t, %1; cvt.u32.u64 %0, t; }" : "=r"(a) : "l"(p));
  return a;
}
__device__ __forceinline__ int elect_one() {
  uint32_t p;
  asm volatile("{ .reg .pred P; elect.sync _|P, 0xFFFFFFFF; selp.b32 %0, 1, 0, P; }" : "=r"(p));
  return (int)p;
}
__device__ __forceinline__ uint64_t make_desc(uint32_t addr) {
  return 0x4000404000010000ULL | (uint64_t)((addr >> 4) & 0x3FFF);
}
__device__ __forceinline__ void mma_f16_ts(uint32_t d, uint32_t a_tmem, uint64_t b,
                                           uint32_t idesc, uint32_t en) {
  asm volatile(
    "{\n\t.reg .pred p;\n\t"
    "setp.ne.u32 p, %4, 0;\n\t"
    "tcgen05.mma.cta_group::1.kind::f16 [%0], [%1], %2, %3, {%5, %5, %5, %5}, p;\n\t}"
    :: "r"(d), "r"(a_tmem), "l"(b), "r"(idesc), "r"(en), "r"(0u) : "memory");
}
__device__ __forceinline__ void mbar_init(uint32_t mbar, uint32_t cnt) {
  asm volatile("mbarrier.init.shared.b64 [%0], %1;" :: "r"(mbar), "r"(cnt) : "memory");
}
__device__ __forceinline__ void mbar_inval(uint32_t mbar) {
  asm volatile("mbarrier.inval.shared.b64 [%0];" :: "r"(mbar) : "memory");
}
__device__ __forceinline__ void mbar_wait(uint32_t mbar, uint32_t parity) {
  asm volatile(
    "{\n\t.reg .pred P;\n\t"
    "WL_%=:\n\t"
    "mbarrier.try_wait.parity.acquire.cta.shared::cta.b64 P, [%0], %1, 0x989680;\n\t"
    "@P bra WD_%=;\n\t"
    "bra WL_%=;\n\t"
    "WD_%=:\n\t}\n"
    :: "r"(mbar), "r"(parity) : "memory");
}
__device__ __forceinline__ void tc_commit(uint32_t mbar) {
  asm volatile(
    "tcgen05.commit.cta_group::1.mbarrier::arrive::one.shared::cluster.b64 [%0];"
    :: "r"(mbar) : "memory");
}
// bulk copy global->smem, completion on mbar (expect_tx + UBLKCP)
__device__ __forceinline__ void bulkCp(uint32_t dst, const void* src, uint32_t bytes,
                                       uint32_t mbar) {
  asm volatile("mbarrier.arrive.expect_tx.shared.b64 _, [%0], %1;"
               :: "r"(mbar), "r"(bytes) : "memory");
  asm volatile(
    "{\n\t.reg .u64 gs;\n\t"
    "cvta.to.global.u64 gs, %1;\n\t"
    "cp.async.bulk.shared::cta.global.mbarrier::complete_tx::bytes [%0], [gs], %2, [%3];\n\t}"
    :: "r"(dst), "l"(src), "r"(bytes), "r"(mbar) : "memory");
}
#define TC_ALLOC(sm, n)   asm volatile("tcgen05.alloc.cta_group::1.sync.aligned.shared::cta.b32 [%0], %1;" :: "r"(sm), "r"(n) : "memory")
#define TC_DEALLOC(t, n)  asm volatile("tcgen05.dealloc.cta_group::1.sync.aligned.b32 %0, %1;" :: "r"(t), "r"(n))
#define TC_RELINQ()       asm volatile("tcgen05.relinquish_alloc_permit.cta_group::1.sync.aligned;")
#define TC_FENCE_AFTER()  asm volatile("tcgen05.fence::after_thread_sync;" ::: "memory")
#define TC_FENCE_BEFORE() asm volatile("tcgen05.fence::before_thread_sync;" ::: "memory")
#define TC_WAIT_LD()      asm volatile("tcgen05.wait::ld.sync.aligned;" ::: "memory")
#define TC_WAIT_ST()      asm volatile("tcgen05.wait::st.sync.aligned;" ::: "memory")

#define TCGEN05_ST_32X32B_X16(tmem_addr, r) \
  asm volatile( \
    "tcgen05.st.sync.aligned.32x32b.x16.b32 [%0], " \
    "{%1, %2, %3, %4, %5, %6, %7, %8, " \
    " %9, %10, %11, %12, %13, %14, %15, %16};" \
    :: "r"(tmem_addr), \
       "r"((r)[0]),  "r"((r)[1]),  "r"((r)[2]),  "r"((r)[3]), \
       "r"((r)[4]),  "r"((r)[5]),  "r"((r)[6]),  "r"((r)[7]), \
       "r"((r)[8]),  "r"((r)[9]),  "r"((r)[10]), "r"((r)[11]), \
       "r"((r)[12]), "r"((r)[13]), "r"((r)[14]), "r"((r)[15]) \
    : "memory")

#define LDTM_X32(r, addr) \
  asm volatile( \
    "tcgen05.ld.sync.aligned.32x32b.x32.b32 " \
    "{%0, %1, %2, %3, %4, %5, %6, %7, " \
    " %8, %9, %10, %11, %12, %13, %14, %15, " \
    " %16, %17, %18, %19, %20, %21, %22, %23, " \
    " %24, %25, %26, %27, %28, %29, %30, %31}, [%32];" \
    : "=r"((r)[0]),  "=r"((r)[1]),  "=r"((r)[2]),  "=r"((r)[3]), \
      "=r"((r)[4]),  "=r"((r)[5]),  "=r"((r)[6]),  "=r"((r)[7]), \
      "=r"((r)[8]),  "=r"((r)[9]),  "=r"((r)[10]), "=r"((r)[11]), \
      "=r"((r)[12]), "=r"((r)[13]), "=r"((r)[14]), "=r"((r)[15]), \
      "=r"((r)[16]), "=r"((r)[17]), "=r"((r)[18]), "=r"((r)[19]), \
      "=r"((r)[20]), "=r"((r)[21]), "=r"((r)[22]), "=r"((r)[23]), \
      "=r"((r)[24]), "=r"((r)[25]), "=r"((r)[26]), "=r"((r)[27]), \
      "=r"((r)[28]), "=r"((r)[29]), "=r"((r)[30]), "=r"((r)[31]) \
    : "r"(addr))

// f16 inputs, f32 acc, M=128, N=128: dtype F32=1<<4, atype/btype F16=0
#define MMA_IDESC 0x8200010u

// TMEM cols (512): D0 @0, D1 @128; A buf b: hi @256+b*128, lo @256+b*128+64
#define TM_D(d)    ((uint32_t)(d) * 128u)
#define TM_AH(b)   (256u + (uint32_t)(b) * 128u)
#define TM_AL(b)   (256u + (uint32_t)(b) * 128u + 64u)

__device__ __forceinline__ uint32_t packh_hi(float a, float b, float& ra, float& rb) {
  __half ha = __float2half(a), hb = __float2half(b);
  ra = a - __half2float(ha); rb = b - __half2float(hb);
  return (uint32_t)__half_as_ushort(ha) | ((uint32_t)__half_as_ushort(hb) << 16);
}
__device__ __forceinline__ uint32_t packh(float a, float b) {
  __half ha = __float2half(a), hb = __float2half(b);
  return (uint32_t)__half_as_ushort(ha) | ((uint32_t)__half_as_ushort(hb) << 16);
}
#endif  // USE_TC

// smem: ctrl 1KB | A bufs 2x64KB | B bufs 2x32KB  = 197632
#define SM_TMEM    0
#define SM_CBAR0   8
#define SM_CBAR1   16
#define SM_ABAR0   24
#define SM_ABAR1   32
#define SM_BBAR0   40
#define SM_BBAR1   48
#define SM_A(b)    (1024 + (b) * 65536)
#define SM_BB(b)   (1024 + 131072 + (b) * 32768)
#define SM_BYTES   (1024 + 131072 + 65536)

// ---------------- simple kernels ------------------------------------------------
__global__ void deg_kernel(ScatParams S) {
  int rel = blockIdx.y;
  int e = blockIdx.x * blockDim.x + threadIdx.x;
  if (e >= EDGES) return;
  const int* ei = S.ei[rel];
  int dstRow = S.flip[rel] ? 0 : EDGES;
  int dst = __ldg(ei + dstRow + e);
  atomicAdd(DEG_PTR + S.aggOff[rel] + dst, 1.0f);
}

__global__ void scatter_kernel(ScatParams S) {
  int rel  = blockIdx.y;
  int lane = threadIdx.x & 31;
  int warp = threadIdx.x >> 5;
  const int* ei   = S.ei[rel];
  const float* xs = S.xsrc[rel];
  float* aggBase  = AGG_PTR + (size_t)S.aggOff[rel] * HDIM;
  int srcRow = S.flip[rel] ? EDGES : 0;
  int dstRow = EDGES - srcRow;
  int e0 = blockIdx.x * 8 + warp;
#pragma unroll
  for (int i = 0; i < 4; ++i) {
    int e   = e0 + i * 75000;
    int src = __ldg(ei + srcRow + e);
    int dst = __ldg(ei + dstRow + e);
    float4 v = __ldg(reinterpret_cast<const float4*>(xs + (size_t)src * HDIM) + lane);
    float* p = aggBase + (size_t)dst * HDIM + lane * 4;
    asm volatile("red.global.add.v4.f32 [%0], {%1,%2,%3,%4};"
                 :: "l"(p), "f"(v.x), "f"(v.y), "f"(v.z), "f"(v.w) : "memory");
  }
}

// ---------------- weight image prep (sum + f32 -> swizzled fp16) --------------
__global__ void bprep_kernel(BPrepParams P) {
  if (blockIdx.x == 36) {
    if (blockIdx.y == 0 && threadIdx.x < 128) {
      for (int j = 0; j < 8; ++j) {
        float s = 0.f;
        for (int q = 0; q < P.bN[j]; ++q) s += __ldg(P.bsrc[j][q] + threadIdx.x);
        g_BSUM[j * 128 + threadIdx.x] = s;
      }
    }
    return;
  }
  int img = blockIdx.x;
  int n = P.nSrc[img];
  char* dst = (char*)g_Bimg + (size_t)img * 32768;
  int lo = blockIdx.y * 4096;
  int hi = lo + 4096;
  for (int idx = lo + threadIdx.x; idx < hi; idx += blockDim.x) {
    int k = idx >> 7, nn = idx & 127;
    float v = 0.f;
    for (int q = 0; q < n; ++q) v += __ldg(P.src[img][q] + idx);
    __half h = __float2half(v);
    uint32_t atom = (uint32_t)(nn >> 3) + (uint32_t)(k >> 6) * 16u;
    uint32_t off  = atom * 1024u + (uint32_t)(nn & 7) * 128u + (uint32_t)(k & 63) * 2u;
    uint32_t sw   = off ^ ((off >> 3) & 0x70);
    *(unsigned short*)(dst + sw) = __half_as_ushort(h);
  }
}

// ---------------- persistent fused GEMM: async-A, fp16 2-term -------------------
// grid=148, 512 threads. A chunks bulk-copied (depth 2) into 2x64KB smem; warps
// 0-7 convert (LDS->fp16 hi/lo->STTM) into double-buffered TMEM. B images bulk-
// copied (depth 1, paced by commit(g-1)) into 2x32KB smem. 16 MMAs/chunk.
// Epilogue warps 12-15 write out the previous tile overlapped.
__global__ __launch_bounds__(512, 1) void gemm_kernel(GemmParams P) {
  extern __shared__ char smem[];
  int tid = threadIdx.x;
  int nTiles = P.rowBlkStart[P.nJobs];

#if USE_TC
  uint32_t sbase = smem_u32(smem);
  int wid = tid >> 5;

  if (wid == 0) { TC_ALLOC(sbase + SM_TMEM, 512); TC_RELINQ(); }
  if (tid == 0) {
    mbar_init(sbase + SM_CBAR0, 1); mbar_init(sbase + SM_CBAR1, 1);
    mbar_init(sbase + SM_ABAR0, 1); mbar_init(sbase + SM_ABAR1, 1);
    mbar_init(sbase + SM_BBAR0, 1); mbar_init(sbase + SM_BBAR1, 1);
  }
  __syncthreads();
  uint32_t tmem;
  asm volatile("ld.shared.b32 %0, [%1];" : "=r"(tmem) : "r"(sbase + SM_TMEM));

  uint32_t woff = ((uint32_t)wid & 3u) << 21;
  uint64_t dbB[2] = { make_desc(sbase + SM_BB(0)), make_desc(sbase + SM_BB(1)) };
  uint32_t cbar[2] = { sbase + SM_CBAR0, sbase + SM_CBAR1 };
  uint32_t abar[2] = { sbase + SM_ABAR0, sbase + SM_ABAR1 };
  uint32_t bbar[2] = { sbase + SM_BBAR0, sbase + SM_BBAR1 };

  auto jobOf = [&](int t) {
    int jj = 0;
#pragma unroll
    for (int q = 1; q < 7; ++q)
      if (q < P.nJobs && t >= P.rowBlkStart[q]) jj = q;
    return jj;
  };
  // advance (tile,c) one chunk; returns false past the end
  auto step = [&](int& t, int& c, int& jj) {
    int nCh = P.nRel[jj] + 1;
    if (++c < nCh) return true;
    c = 0; t += gridDim.x;
    if (t >= nTiles) return false;
    jj = jobOf(t);
    return true;
  };
  // A source for (job, tile-row0, c): ptr + clamped byte count
  auto issueA = [&](int jj, int t, int c, int buf) {
    int row0 = (t - P.rowBlkStart[jj]) * 128;
    int rows = P.nRows[jj] - row0; if (rows > 128) rows = 128;
    const float* src;
    if (c == 0) src = P.xCur[jj] + (size_t)row0 * HDIM;
    else src = AGG_PTR + (size_t)(P.aggOff[jj][c - 1] + row0) * HDIM;
    bulkCp(sbase + SM_A(buf), src, (uint32_t)rows * 512u, abar[buf]);
  };
  auto issueB = [&](int jj, int c, int buf) {
    bulkCp(sbase + SM_BB(buf), (const char*)g_Bimg + (size_t)P.bimg[jj][c] * 32768,
           32768u, bbar[buf]);
  };

  // convert: row = tid&127, half = tid>>7 (warps 0-7)
  auto convert = [&](int jj, int row0, int nrows, int c, int buf) {
    int r = tid & 127, half = tid >> 7;
    int gr = row0 + r;
    bool av = gr < nrows;
    float sc = 1.0f;
    if (c > 0 && av) sc = 1.0f / fmaxf(__ldg(DEG_PTR + P.degOff[jj][c - 1] + gr), 1.0f);
    const float4* as = reinterpret_cast<const float4*>(smem + SM_A(buf) + r * 512 + half * 256);
#pragma unroll
    for (int g2 = 0; g2 < 2; ++g2) {
      uint32_t hv[16], lv[16];
#pragma unroll
      for (int i = 0; i < 8; ++i) {
        float4 v = av ? as[g2 * 8 + i] : make_float4(0.f, 0.f, 0.f, 0.f);
        float ax = v.x * sc, ay = v.y * sc, az = v.z * sc, aw = v.w * sc;
        float rx, ry, rz, rw;
        hv[2 * i]     = packh_hi(ax, ay, rx, ry);
        hv[2 * i + 1] = packh_hi(az, aw, rz, rw);
        lv[2 * i]     = packh(rx, ry);
        lv[2 * i + 1] = packh(rz, rw);
      }
      uint32_t coff = (uint32_t)(half * 32 + g2 * 16);
      TCGEN05_ST_32X32B_X16(tmem + TM_AH(buf) + coff + woff, hv);
      TCGEN05_ST_32X32B_X16(tmem + TM_AL(buf) + coff + woff, lv);
    }
    TC_WAIT_ST();
    TC_FENCE_BEFORE();
  };

  auto dispatch = [&](int c, int buf, int dpar) {
    TC_FENCE_AFTER();
    uint32_t en = (c > 0) ? 1u : 0u;
    uint32_t dst = tmem + TM_D(dpar);
#pragma unroll
    for (int ks = 0; ks < 8; ++ks) {
      uint64_t boff = (ks < 4) ? (uint64_t)(ks * 2) : (uint64_t)(1024 + (ks - 4) * 2);
      mma_f16_ts(dst, tmem + TM_AH(buf) + (uint32_t)ks * 8u, dbB[buf] + boff, MMA_IDESC, en);
      en = 1u;
      mma_f16_ts(dst, tmem + TM_AL(buf) + (uint32_t)ks * 8u, dbB[buf] + boff, MMA_IDESC, 1u);
    }
    tc_commit(cbar[buf]);   // commit(g) -> CBAR[g&1]
  };

  auto epilogue = [&](int pj, int prow0, int pnrows, int pd) {
    TC_FENCE_AFTER();
    int lid = tid & 31;
    int sub = wid & 3;
    int gr = prow0 + sub * 32 + lid;
    const float* bs = g_BSUM + P.bsumIdx[pj] * 128;
    float* op = P.outPtr[pj] + (size_t)gr * HDIM;
#pragma unroll
    for (int nb = 0; nb < 4; ++nb) {
      uint32_t dr[32];
      LDTM_X32(dr, tmem + TM_D(pd) + nb * 32);
      TC_WAIT_LD();
      if (gr < pnrows) {
#pragma unroll
        for (int q = 0; q < 32; q += 4) {
          float4 o;
          o.x = __uint_as_float(dr[q + 0]) + __ldg(bs + nb * 32 + q + 0);
          o.y = __uint_as_float(dr[q + 1]) + __ldg(bs + nb * 32 + q + 1);
          o.z = __uint_as_float(dr[q + 2]) + __ldg(bs + nb * 32 + q + 2);
          o.w = __uint_as_float(dr[q + 3]) + __ldg(bs + nb * 32 + q + 3);
          if (P.relu) {
            o.x = fmaxf(o.x, 0.f); o.y = fmaxf(o.y, 0.f);
            o.z = fmaxf(o.z, 0.f); o.w = fmaxf(o.w, 0.f);
          }
          *reinterpret_cast<float4*>(op + nb * 32 + q) = o;
        }
      }
    }
    TC_FENCE_BEFORE();
  };

  // --- prologue: issue A(0),A(1),B(0),B(1) ---
  int tile = blockIdx.x;
  bool valid = tile < nTiles;
  int j = valid ? jobOf(tile) : 0;
  if (valid && tid == 0) {
    int t1 = tile, c1 = 1, j1 = j;       // chunk 1 exists (every tile has >=2 chunks)
    issueA(j, tile, 0, 0);
    issueA(j1, t1, c1, 1);
    issueB(j, 0, 0);
    issueB(j1, c1, 1);
  }

  // phase trackers (uniform across threads)
  uint32_t paA[2] = {0u, 0u}, paB[2] = {0u, 0u};
  uint32_t pcMain[2] = {0u, 0u}, pc257[2] = {0u, 0u};

  int c = 0, g = 0, tcount = 0;
  int prevJ = -1, prevRow0 = 0, prevNrows = 0, prevD = 0;

  while (valid) {
    int buf = g & 1;
    int row0  = (tile - P.rowBlkStart[j]) * 128;
    int nrows = P.nRows[j];
    int nCh   = P.nRel[j] + 1;
    int dpar  = tcount & 1;

    // pace: commit(g-2) done -> A-TMEM(buf) + B smem(buf) reusable, D ok
    if (g >= 2) { mbar_wait(cbar[buf], pcMain[buf]); pcMain[buf] ^= 1; }
    // A(g) landed
    mbar_wait(abar[buf], paA[buf]); paA[buf] ^= 1;

    if (tid < 256) {
      convert(j, row0, nrows, c, buf);
    } else if (wid >= 12) {
      if (c == 1 && prevJ >= 0) epilogue(prevJ, prevRow0, prevNrows, prevD);
    }
    __syncthreads();   // convert done: smem A(buf) free

    // lookaheads
    int tA = tile, cA = c, jA = j; bool vA = step(tA, cA, jA) && step(tA, cA, jA); // g+2
    int tB = tile, cB = c, jB = j; bool vB = step(tB, cB, jB);                    // g+1

    if (tid == 256) {
      if (vA) issueA(jA, tA, cA, buf);          // A(g+2) into freed buf
    } else if (tid == 257) {
      if (g >= 1 && vB) {
        // B(g+1) into buf((g+1)&1): safe once commit(g-1) observed
        mbar_wait(cbar[(g - 1) & 1], pc257[(g - 1) & 1]); pc257[(g - 1) & 1] ^= 1;
        issueB(jB, cB, (g + 1) & 1);
      }
    } else if (wid == 0 && elect_one()) {
      mbar_wait(bbar[buf], paB[buf]);           // B(g) landed
      dispatch(c, buf, dpar);
    }
    paB[buf] ^= 1;   // uniform flip (only dispatch lane waited)
    if (g >= 1) pc257[(g - 1) & 1] = pc257[(g - 1) & 1];  // (kept uniform: only 257 flips; others don't read it)

    // advance
    if (c == nCh - 1) { prevJ = j; prevRow0 = row0; prevNrows = nrows; prevD = dpar; ++tcount; }
    valid = step(tile, c, j);
    ++g;
  }

  // drain: commits g-2, g-1
  if (g >= 2) { int b = (g - 2) & 1; mbar_wait(cbar[b], pcMain[b]); pcMain[b] ^= 1; }
  if (g >= 1) { int b = (g - 1) & 1; mbar_wait(cbar[b], pcMain[b]); pcMain[b] ^= 1; }
  if (wid >= 12 && prevJ >= 0) epilogue(prevJ, prevRow0, prevNrows, prevD);

  __syncthreads();
  if (tid == 0) {
    mbar_inval(sbase + SM_CBAR0); mbar_inval(sbase + SM_CBAR1);
    mbar_inval(sbase + SM_ABAR0); mbar_inval(sbase + SM_ABAR1);
    mbar_inval(sbase + SM_BBAR0); mbar_inval(sbase + SM_BBAR1);
  }
  __syncthreads();
  if (wid == 0) TC_DEALLOC(tmem, 512);

#else  // ---------------- fallback for non-"a" PTX pass (never executes) --------
  (void)P; (void)nTiles; (void)tid;
#endif
}

// final: out[50000,64] = CRS[50000,128] @ linW[128,64] + linb
__global__ void final_kernel(const float* __restrict__ W,
                             const float* __restrict__ b,
                             float* __restrict__ out) {
  __shared__ float sW[128 * 64];
  __shared__ float sx[4][128];
  int tid = threadIdx.x;
  for (int i = tid; i < 128 * 64; i += 256) sW[i] = W[i];
  int n = tid & 63, rl = tid >> 6;
  int row = blockIdx.x * 4 + rl;
  for (int k = n; k < 128; k += 64)
    sx[rl][k] = (row < 50000) ? g_CRS[(size_t)row * HDIM + k] : 0.f;
  __syncthreads();
  float acc = 0.f;
#pragma unroll 16
  for (int k = 0; k < 128; ++k) acc += sx[rl][k] * sW[k * 64 + n];
  if (row < 50000) out[(size_t)row * 64 + n] = acc + b[n];
}

// ---------------- launch --------------------------------------------------------
extern "C" void kernel_launch(void* const* d_in, const int* in_sizes, int n_in,
                              void* d_out, int out_size) {
  (void)in_sizes; (void)n_in; (void)out_size;
  const float* X[10];
  for (int t = 0; t < 10; ++t) X[t] = (const float*)d_in[t];
  const int* EI[13];
  for (int i = 0; i < 13; ++i) EI[i] = (const int*)d_in[10 + i];
  const float* Wl   = (const float*)d_in[23];
  const float* bl   = (const float*)d_in[24];
  const float* Wr   = (const float*)d_in[25];
  const float* linW = (const float*)d_in[26];
  const float* linb = (const float*)d_in[27];
  float* out = (float*)d_out;

  void *pZBUF = 0, *pXBUF = 0, *pCRS = 0;
  cudaGetSymbolAddress(&pZBUF, g_ZBUF);
  cudaGetSymbolAddress(&pXBUF, g_XBUF);
  cudaGetSymbolAddress(&pCRS, g_CRS);
  float* XBUF = (float*)pXBUF;
  float* CRS = (float*)pCRS;

  cudaFuncSetAttribute(gemm_kernel, cudaFuncAttributeMaxDynamicSharedMemorySize, SM_BYTES);

  static const int TYPE_OFF[7] = {0, 50000, 52000, 132000, 142000, 144000, 294000};

  long long degOff[26];
  {
    long long cum = 0;
    for (int k = 0; k < 22; ++k) { int r = L1_RELS[k]; degOff[r] = cum; cum += NODE_N[REL[r].d]; }
  }

  ScatParams s1 = {};
  for (int k = 0; k < 22; ++k) {
    int r = L1_RELS[k];
    s1.ei[k] = EI[REL[r].ei];
    s1.xsrc[k] = X[REL[r].s];
    s1.aggOff[k] = degOff[r];
    s1.flip[k] = REL[r].flip;
  }
  ScatParams s2 = {};
  for (int k = 0; k < 6; ++k) {
    int r = L2_RELS[k];
    s2.ei[k] = EI[REL[r].ei];
    s2.xsrc[k] = XBUF + (size_t)TYPE_OFF[REL[r].s] * HDIM;
    s2.aggOff[k] = (long long)k * 50000;
    s2.flip[k] = REL[r].flip;
  }

  BPrepParams bp = {};
  int img = 0;

  GemmParams g1 = {};
  g1.nJobs = 7; g1.relu = 1;
  int cumblk = 0;
  for (int t = 0; t < 7; ++t) {
    g1.rowBlkStart[t] = cumblk;
    cumblk += (NODE_N[t] + 127) / 128;
    g1.nRows[t] = NODE_N[t];
    g1.xCur[t] = X[t];
    g1.outPtr[t] = XBUF + (size_t)TYPE_OFF[t] * HDIM;
    g1.bsumIdx[t] = t;
    int n = 0;
    g1.bimg[t][0] = img;
    for (int k = 0; k < 22; ++k) {
      int r = L1_RELS[k];
      if (REL[r].d == t) { bp.src[img][n] = Wr + (size_t)r * 16384; ++n; }
    }
    bp.nSrc[img] = n; ++img;
    n = 0;
    for (int k = 0; k < 22; ++k) {
      int r = L1_RELS[k];
      if (REL[r].d == t) {
        g1.bimg[t][1 + n] = img;
        bp.src[img][0] = Wl + (size_t)r * 16384; bp.nSrc[img] = 1; ++img;
        g1.aggOff[t][n] = degOff[r];
        g1.degOff[t][n] = degOff[r];
        ++n;
      }
    }
    g1.nRel[t] = n;
  }
  g1.rowBlkStart[7] = cumblk;

  GemmParams g2 = {};
  g2.nJobs = 1; g2.relu = 1;
  int g2blocks = (NODE_N[0] + 127) / 128;
  g2.rowBlkStart[0] = 0; g2.rowBlkStart[1] = g2blocks;
  g2.nRows[0] = NODE_N[0];
  g2.xCur[0] = XBUF;
  g2.outPtr[0] = CRS;
  g2.bsumIdx[0] = 7;
  g2.nRel[0] = 6;
  g2.bimg[0][0] = img;
  for (int k = 0; k < 6; ++k) bp.src[img][k] = Wr + ((size_t)26 + L2_RELS[k]) * 16384;
  bp.nSrc[img] = 6; ++img;
  for (int k = 0; k < 6; ++k) {
    int r = L2_RELS[k];
    g2.bimg[0][1 + k] = img;
    bp.src[img][0] = Wl + ((size_t)26 + r) * 16384; bp.nSrc[img] = 1; ++img;
    g2.aggOff[0][k] = (long long)k * 50000;
    g2.degOff[0][k] = degOff[r];
  }
  int nImgs = img;   // 36

  for (int t = 0; t < 7; ++t) {
    int n = 0;
    for (int k = 0; k < 22; ++k) {
      int r = L1_RELS[k];
      if (REL[r].d == t) bp.bsrc[t][n++] = bl + (size_t)r * 128;
    }
    bp.bN[t] = n;
  }
  for (int k = 0; k < 6; ++k) bp.bsrc[7][k] = bl + ((size_t)26 + L2_RELS[k]) * 128;
  bp.bN[7] = 6;

  // ---- execution ----
  cudaMemsetAsync(pZBUF, 0, ((size_t)L1_ROWS * HDIM + L1_ROWS) * sizeof(float), 0);
  deg_kernel<<<dim3((EDGES + 255) / 256, 22), 256>>>(s1);
  bprep_kernel<<<dim3(nImgs + 1, 4), 256>>>(bp);
  scatter_kernel<<<dim3(9375, 22), 256>>>(s1);
  gemm_kernel<<<148, 512, SM_BYTES>>>(g1);

  cudaMemsetAsync(pZBUF, 0, (size_t)300000 * HDIM * sizeof(float), 0);
  scatter_kernel<<<dim3(9375, 6), 256>>>(s2);
  gemm_kernel<<<148, 512, SM_BYTES>>>(g2);
  final_kernel<<<(50000 + 3) / 4, 256>>>(linW, linb, out);
}